// round 11
// baseline (speedup 1.0000x reference)
#include <cuda_runtime.h>
#include <cuda_bf16.h>
#include <cstdint>

// ---------------- problem constants ----------------
#define BATCH    256
#define FEAT     1500
#define FEAT_PAD 1504          // 47 * 32, padded K for decoder
#define INSZ     28224
#define SPLITK   12
#define ENC_KBLK_TOTAL 882     // 28224 / 32
#define ENC_KBLK_PER_SPLIT 74  // 11*74 + 68 = 882
#define DEC_KBLK 47            // 1504 / 32

// ---------------- GEMM tile config -----------------
#define BM 128
#define BN 128
#define BK 32                  // K elements per chunk (64B of bf16 per row)
#define NTH 256                // 8 warps: 2 (M) x 4 (N), warp tile 64x32

// smem tiles: 128 rows x 64B payload, padded to 80B rows (conflict-free ldmatrix)
#define ROWB   80
#define TILE_B (128 * ROWB)            // 10240
#define A_STAGE (2 * TILE_B)           // hi + lo = 20480
#define B_STAGE (2 * TILE_B)           // 20480
#define SMEM_A_REGION (3 * A_STAGE)    // 61440 (3-stage cp.async ring)
#define SMEM_TOTAL (SMEM_A_REGION + 2 * B_STAGE)   // 102400 -> 2 CTAs = 200KB

// ---------------- scratch ----------------
__device__ float g_preact[SPLITK * BATCH * FEAT];                    // 18.4 MB
__device__ __align__(256) __nv_bfloat16 g_xhi[BATCH * INSZ];
__device__ __align__(256) __nv_bfloat16 g_xlo[BATCH * INSZ];
__device__ __align__(256) __nv_bfloat16 g_yhi[BATCH * FEAT_PAD];
__device__ __align__(256) __nv_bfloat16 g_ylo[BATCH * FEAT_PAD];
__device__ float g_rownorm2[FEAT];

// ---------------- helpers ----------------
__device__ __forceinline__ uint32_t smem_u32(const void* p) {
    uint32_t a;
    asm("{ .reg .u64 t; cvta.to.shared.u64 t, %1; cvt.u32.u64 %0, t; }" : "=r"(a) : "l"(p));
    return a;
}
__device__ __forceinline__ float sigmoidf_(float z) { return 1.0f / (1.0f + __expf(-z)); }

__device__ __forceinline__ void cpa16(uint32_t dst_smem, const void* src) {
    asm volatile("cp.async.cg.shared.global [%0], [%1], 16;" :: "r"(dst_smem), "l"(src));
}
#define CP_COMMIT() asm volatile("cp.async.commit_group;" ::: "memory")
#define CP_WAIT1()  asm volatile("cp.async.wait_group 1;" ::: "memory")

// split f32 pair (x=k, y=k+1) -> packed bf16x2 hi and lo words (k in low half)
__device__ __forceinline__ void split_pair(float x, float y, uint32_t& hw, uint32_t& lw) {
    uint32_t h;
    asm("cvt.rn.bf16x2.f32 %0, %1, %2;" : "=r"(h) : "f"(y), "f"(x));
    float hx = __uint_as_float(h << 16);
    float hy = __uint_as_float(h & 0xffff0000u);
    float lx = x - hx, ly = y - hy;
    asm("cvt.rn.bf16x2.f32 %0, %1, %2;" : "=r"(lw) : "f"(ly), "f"(lx));
    hw = h;
}

__device__ __forceinline__ void ldmx4(uint32_t r[4], uint32_t addr) {
    asm volatile("ldmatrix.sync.aligned.m8n8.x4.shared.b16 {%0,%1,%2,%3}, [%4];"
                 : "=r"(r[0]), "=r"(r[1]), "=r"(r[2]), "=r"(r[3]) : "r"(addr));
}
__device__ __forceinline__ void mma16816(float c[4], const uint32_t a[4], uint32_t b0, uint32_t b1) {
    asm volatile(
        "mma.sync.aligned.m16n8k16.row.col.f32.bf16.bf16.f32 "
        "{%0,%1,%2,%3}, {%4,%5,%6,%7}, {%8,%9}, {%0,%1,%2,%3};"
        : "+f"(c[0]), "+f"(c[1]), "+f"(c[2]), "+f"(c[3])
        : "r"(a[0]), "r"(a[1]), "r"(a[2]), "r"(a[3]), "r"(b0), "r"(b1));
}

// ---------------------------------------------------------------------------
// split-bf16 HMMA GEMM: C[m,n] = sum_k A[m,k] * B[n,k]
//   A: pre-split bf16 hi/lo arrays [rows][ldaE], all K valid (zero-padded)
//   B: f32 [N][ldb], K valid in [0, kvalidB); split to bf16 hi/lo in-loop
//   mode 0: raw f32 partial -> C + z*BATCH*ldc ; fused W row-norms (y==0)
//   mode 1: sigmoid(acc + bias[n]) -> C
// ---------------------------------------------------------------------------
__global__ void __launch_bounds__(NTH, 2)
gemm_hmma(const __nv_bfloat16* __restrict__ Ahi, const __nv_bfloat16* __restrict__ Alo,
          const float* __restrict__ B, const float* __restrict__ bias,
          float* __restrict__ C,
          int N, int ldaE, int ldb, int kvalidB, int ldc,
          int kblk_per_split, int kblk_total, int mode)
{
    extern __shared__ char smem[];
    const uint32_t sb = smem_u32(smem);
    const int tid = threadIdx.x, wid = tid >> 5, lane = tid & 31;
    const int bm = blockIdx.y * BM;
    const int bn = blockIdx.x * BN;
    const int z  = blockIdx.z;
    const int kb0 = z * kblk_per_split;
    int nch = kblk_total - kb0;
    if (nch > kblk_per_split) nch = kblk_per_split;
    if (nch <= 0) return;

    const int wm = wid >> 2;            // 0..1 -> m offset wm*64
    const int wn = wid & 3;             // 0..3 -> n offset wn*32

    // loader mapping: 2 threads per row
    const int crow  = tid >> 1;         // 0..127
    const int chalf = tid & 1;          // half-row (16 elements / 32B hi bytes)
    const int gnB   = bn + crow;
    const int gnBc  = gnB < N ? gnB : N - 1;

    float acc[4][4][4];
    #pragma unroll
    for (int i = 0; i < 4; i++)
        #pragma unroll
        for (int j = 0; j < 4; j++)
            #pragma unroll
            for (int q = 0; q < 4; q++) acc[i][j][q] = 0.f;

    float rn = 0.f;          // fused row-norm accumulator (mode 0)
    float4 bv[4];            // B prefetch registers (16 floats)

    // ---- A tile copy via cp.async (bf16 hi/lo, no conversion) ----
    auto cpA = [&](int c) {
        const uint32_t dA = sb + (uint32_t)((c % 3) * A_STAGE) + crow * ROWB + chalf * 32;
        const size_t eoff = (size_t)(bm + crow) * ldaE + (size_t)(kb0 + c) * BK + chalf * 16;
        const char* srcH = (const char*)(Ahi + eoff);
        const char* srcL = (const char*)(Alo + eoff);
        cpa16(dA, srcH);                 cpa16(dA + 16, srcH + 16);
        cpa16(dA + TILE_B, srcL);        cpa16(dA + TILE_B + 16, srcL + 16);
    };
    // ---- B tile: LDG f32 into regs ----
    auto ldgB = [&](int c) {
        const int kc = (kb0 + c) * BK + chalf * 16;
        const float* p = B + (size_t)gnBc * ldb + kc;
        #pragma unroll
        for (int j = 0; j < 4; j++) {
            bool ok = (gnB < N) && (kc + j * 4 < kvalidB);
            bv[j] = ok ? *reinterpret_cast<const float4*>(p + j * 4)
                       : make_float4(0.f, 0.f, 0.f, 0.f);
        }
    };
    // ---- split + STS B tile (also row-norm accumulation) ----
    auto stsB = [&](int c) {
        char* d = smem + SMEM_A_REGION + (c & 1) * B_STAGE + crow * ROWB + chalf * 32;
        uint32_t h[8], l[8];
        #pragma unroll
        for (int j = 0; j < 4; j++) {
            split_pair(bv[j].x, bv[j].y, h[2 * j],     l[2 * j]);
            split_pair(bv[j].z, bv[j].w, h[2 * j + 1], l[2 * j + 1]);
            if (mode == 0)
                rn += bv[j].x * bv[j].x + bv[j].y * bv[j].y
                    + bv[j].z * bv[j].z + bv[j].w * bv[j].w;
        }
        *reinterpret_cast<uint4*>(d)               = make_uint4(h[0], h[1], h[2], h[3]);
        *reinterpret_cast<uint4*>(d + 16)          = make_uint4(h[4], h[5], h[6], h[7]);
        *reinterpret_cast<uint4*>(d + TILE_B)      = make_uint4(l[0], l[1], l[2], l[3]);
        *reinterpret_cast<uint4*>(d + TILE_B + 16) = make_uint4(l[4], l[5], l[6], l[7]);
    };

    // ---- prologue ----
    cpA(0); CP_COMMIT();
    if (1 < nch) cpA(1);
    CP_COMMIT();
    ldgB(0); stsB(0);

    const int lr = lane & 15;      // row within 16-row tile
    const int lc = lane >> 4;      // 0/1 -> +16B (k8..15 half)

    for (int ci = 0; ci < nch; ci++) {
        CP_WAIT1();                // A(ci) arrived (A(ci+1) may be in flight)
        __syncthreads();           // B STS(ci) visible; compute(ci-1) done everywhere

        if (ci + 2 < nch) cpA(ci + 2);   // into A stage (ci-1)%3: free
        CP_COMMIT();                     // always commit (empty groups keep count)
        if (ci + 1 < nch) ldgB(ci + 1);

        // ---- compute chunk ci ----
        const uint32_t saB = sb + (uint32_t)((ci % 3) * A_STAGE);
        const uint32_t sbB = sb + (uint32_t)(SMEM_A_REGION + (ci & 1) * B_STAGE);
        #pragma unroll
        for (int ks = 0; ks < 2; ks++) {
            uint32_t bh[4][2], bl[4][2];
            const uint32_t boff = sbB + (uint32_t)((wn * 32 + lr) * ROWB + ks * 32 + lc * 16);
            #pragma unroll
            for (int bt = 0; bt < 2; bt++) {
                uint32_t t[4];
                ldmx4(t, boff + bt * 16 * ROWB);
                bh[bt * 2 + 0][0] = t[0]; bh[bt * 2 + 0][1] = t[2];
                bh[bt * 2 + 1][0] = t[1]; bh[bt * 2 + 1][1] = t[3];
                ldmx4(t, boff + TILE_B + bt * 16 * ROWB);
                bl[bt * 2 + 0][0] = t[0]; bl[bt * 2 + 0][1] = t[2];
                bl[bt * 2 + 1][0] = t[1]; bl[bt * 2 + 1][1] = t[3];
            }
            const uint32_t aoff = saB + (uint32_t)((wm * 64 + lr) * ROWB + ks * 32 + lc * 16);
            #pragma unroll
            for (int mi = 0; mi < 4; mi++) {
                uint32_t ah[4], al[4];
                ldmx4(ah, aoff + mi * 16 * ROWB);
                ldmx4(al, aoff + TILE_B + mi * 16 * ROWB);
                #pragma unroll
                for (int ni = 0; ni < 4; ni++)
                    mma16816(acc[mi][ni], ah, bh[ni][0], bh[ni][1]);
                #pragma unroll
                for (int ni = 0; ni < 4; ni++)
                    mma16816(acc[mi][ni], al, bh[ni][0], bh[ni][1]);
                #pragma unroll
                for (int ni = 0; ni < 4; ni++)
                    mma16816(acc[mi][ni], ah, bl[ni][0], bl[ni][1]);
            }
        }

        if (ci + 1 < nch) stsB(ci + 1);   // other B buffer: safe after top sync
    }

    // ---- fused row-norm output (encoder, one grid.y slice only) ----
    if (mode == 0 && blockIdx.y == 0) {
        rn += __shfl_xor_sync(0xffffffffu, rn, 1);
        if (chalf == 0 && gnB < N) atomicAdd(&g_rownorm2[gnB], rn);
    }

    // ---- epilogue ----
    const int er = lane >> 2, ec = (lane & 3) * 2;
    #pragma unroll
    for (int mi = 0; mi < 4; mi++) {
        #pragma unroll
        for (int ni = 0; ni < 4; ni++) {
            int m0 = bm + wm * 64 + mi * 16 + er;
            int n0 = bn + wn * 32 + ni * 8 + ec;
            if (mode == 0) {
                float* Cz = C + (size_t)z * BATCH * ldc;
                if (n0 + 1 < N) {
                    *reinterpret_cast<float2*>(Cz + (size_t)m0 * ldc + n0) =
                        make_float2(acc[mi][ni][0], acc[mi][ni][1]);
                    *reinterpret_cast<float2*>(Cz + (size_t)(m0 + 8) * ldc + n0) =
                        make_float2(acc[mi][ni][2], acc[mi][ni][3]);
                } else if (n0 < N) {
                    Cz[(size_t)m0 * ldc + n0] = acc[mi][ni][0];
                    Cz[(size_t)(m0 + 8) * ldc + n0] = acc[mi][ni][2];
                }
            } else {
                if (n0 + 1 < N) {
                    float b0 = bias[n0], b1 = bias[n0 + 1];
                    *reinterpret_cast<float2*>(C + (size_t)m0 * ldc + n0) =
                        make_float2(sigmoidf_(acc[mi][ni][0] + b0), sigmoidf_(acc[mi][ni][1] + b1));
                    *reinterpret_cast<float2*>(C + (size_t)(m0 + 8) * ldc + n0) =
                        make_float2(sigmoidf_(acc[mi][ni][2] + b0), sigmoidf_(acc[mi][ni][3] + b1));
                } else if (n0 < N) {
                    float b0 = bias[n0];
                    C[(size_t)m0 * ldc + n0] = sigmoidf_(acc[mi][ni][0] + b0);
                    C[(size_t)(m0 + 8) * ldc + n0] = sigmoidf_(acc[mi][ni][2] + b0);
                }
            }
        }
    }
}

// ---------------------------------------------------------------------------
// x f32 -> x_hi/x_lo bf16 ; zero row-norm accumulators + jac
// ---------------------------------------------------------------------------
__global__ void convert_x(const float4* __restrict__ x4, float* __restrict__ jac_init) {
    int i = blockIdx.x * 256 + threadIdx.x;
    if (i < BATCH * INSZ / 4) {
        float4 v = x4[i];
        uint32_t h0, l0, h1, l1;
        split_pair(v.x, v.y, h0, l0);
        split_pair(v.z, v.w, h1, l1);
        reinterpret_cast<uint2*>(g_xhi)[i] = make_uint2(h0, h1);
        reinterpret_cast<uint2*>(g_xlo)[i] = make_uint2(l0, l1);
    }
    if (i < FEAT) g_rownorm2[i] = 0.f;
    if (i == 0) *jac_init = 0.f;
}

// ---------------------------------------------------------------------------
// encoder epilogue: sum split-K partials + bias -> sigmoid -> y_enc hi/lo bf16,
// accumulate jac_reg (row norms came from the fused encoder GEMM)
// ---------------------------------------------------------------------------
__global__ void enc_epilogue(const float* __restrict__ b_enc, float* __restrict__ jac_out) {
    int idx = blockIdx.x * blockDim.x + threadIdx.x;
    float part = 0.f;
    if (idx < BATCH * FEAT_PAD) {
        int m = idx / FEAT_PAD, f = idx % FEAT_PAD;
        if (f < FEAT) {
            float zsum = b_enc[f];
            int base = m * FEAT + f;
            #pragma unroll
            for (int s = 0; s < SPLITK; s++)
                zsum += g_preact[(size_t)s * BATCH * FEAT + base];
            float y = sigmoidf_(zsum);
            __nv_bfloat16 yh = __float2bfloat16_rn(y);
            g_yhi[idx] = yh;
            g_ylo[idx] = __float2bfloat16_rn(y - __bfloat162float(yh));
            float sd = y * (1.f - y);
            part = sd * sd * g_rownorm2[f];
        } else {
            g_yhi[idx] = __float2bfloat16_rn(0.f);
            g_ylo[idx] = __float2bfloat16_rn(0.f);
        }
    }
    #pragma unroll
    for (int o = 16; o > 0; o >>= 1) part += __shfl_down_sync(0xffffffffu, part, o);
    __shared__ float wsum[8];
    int lane = threadIdx.x & 31, wid = threadIdx.x >> 5;
    if (lane == 0) wsum[wid] = part;
    __syncthreads();
    if (wid == 0) {
        float v = (lane < 8) ? wsum[lane] : 0.f;
        #pragma unroll
        for (int o = 4; o > 0; o >>= 1) v += __shfl_down_sync(0xffffffffu, v, o);
        if (lane == 0) atomicAdd(jac_out, v);
    }
}

// ---------------------------------------------------------------------------
extern "C" void kernel_launch(void* const* d_in, const int* in_sizes, int n_in,
                              void* d_out, int out_size) {
    const float* x     = (const float*)d_in[0];
    const float* W_enc = (const float*)d_in[1];
    const float* b_enc = (const float*)d_in[2];
    const float* W_dec = (const float*)d_in[3];
    const float* b_dec = (const float*)d_in[4];
    float* out = (float*)d_out;
    float* jac = out + (out_size - 1);

    float* preact;
    __nv_bfloat16 *xhi, *xlo, *yhi, *ylo;
    cudaGetSymbolAddress((void**)&preact, g_preact);
    cudaGetSymbolAddress((void**)&xhi, g_xhi);
    cudaGetSymbolAddress((void**)&xlo, g_xlo);
    cudaGetSymbolAddress((void**)&yhi, g_yhi);
    cudaGetSymbolAddress((void**)&ylo, g_ylo);

    cudaFuncSetAttribute(gemm_hmma, cudaFuncAttributeMaxDynamicSharedMemorySize, SMEM_TOTAL);

    // 1) x -> bf16 hi/lo split; zero rownorm + jac
    convert_x<<<(BATCH * INSZ / 4 + 255) / 256, 256>>>((const float4*)x, jac);

    // 2) encoder GEMM (fused W_enc row norms): split-K=12 -> 288 CTAs
    {
        dim3 grid((FEAT + BN - 1) / BN, BATCH / BM, SPLITK);   // (12, 2, 12)
        gemm_hmma<<<grid, NTH, SMEM_TOTAL>>>(
            xhi, xlo, W_enc, nullptr, preact,
            FEAT, INSZ, INSZ, INSZ, FEAT,
            ENC_KBLK_PER_SPLIT, ENC_KBLK_TOTAL, 0);
    }

    // 3) bias + sigmoid -> y_enc hi/lo bf16; jacobian reduction
    enc_epilogue<<<(BATCH * FEAT_PAD + 255) / 256, 256>>>(b_enc, jac);

    // 4) decoder GEMM with fused bias+sigmoid
    {
        dim3 grid((INSZ + BN - 1) / BN, BATCH / BM, 1);        // (221, 2, 1)
        gemm_hmma<<<grid, NTH, SMEM_TOTAL>>>(
            yhi, ylo, W_dec, b_dec, out,
            INSZ, FEAT_PAD, FEAT, FEAT, INSZ,
            DEC_KBLK, DEC_KBLK, 1);
    }
}

// round 12
// speedup vs baseline: 1.1297x; 1.1297x over previous
#include <cuda_runtime.h>
#include <cuda_bf16.h>
#include <cstdint>

// ---------------- problem constants ----------------
#define BATCH    256
#define FEAT     1500
#define FEAT_PAD 1504          // 94 * 16, padded K for decoder
#define INSZ     28224
#define SPLITK   12
#define ENC_KBLK_TOTAL 1764    // 28224 / 16
#define ENC_KBLK_PER_SPLIT 147 // 12 * 147 exactly
#define DEC_KBLK 94            // 1504 / 16

// ---------------- GEMM tile config -----------------
#define BM 128
#define BN 128
#define BK 16                  // K elements per chunk (32B bf16 payload per row)
#define NTH 256                // 8 warps: 2 (M) x 4 (N), warp tile 64x32

// smem tiles: 128 rows x 32B payload, padded to 48B rows (conflict-free ldmatrix)
#define ROWB   48
#define TILE_B (128 * ROWB)            // 6144
#define A_STAGE (2 * TILE_B)           // hi + lo = 12288
#define B_STAGE (2 * TILE_B)           // 12288
#define SMEM_A_REGION (3 * A_STAGE)    // 36864 (3-stage cp.async ring)
#define SMEM_TOTAL (SMEM_A_REGION + 2 * B_STAGE)   // 61440 -> 2 CTAs = 120KB

// ---------------- scratch ----------------
__device__ float g_preact[SPLITK * BATCH * FEAT];                    // 18.4 MB
__device__ __align__(256) __nv_bfloat16 g_xhi[BATCH * INSZ];
__device__ __align__(256) __nv_bfloat16 g_xlo[BATCH * INSZ];
__device__ __align__(256) __nv_bfloat16 g_yhi[BATCH * FEAT_PAD];
__device__ __align__(256) __nv_bfloat16 g_ylo[BATCH * FEAT_PAD];
__device__ float g_rownorm2[FEAT];

// ---------------- helpers ----------------
__device__ __forceinline__ uint32_t smem_u32(const void* p) {
    uint32_t a;
    asm("{ .reg .u64 t; cvta.to.shared.u64 t, %1; cvt.u32.u64 %0, t; }" : "=r"(a) : "l"(p));
    return a;
}
__device__ __forceinline__ float sigmoidf_(float z) { return 1.0f / (1.0f + __expf(-z)); }

__device__ __forceinline__ void cpa16(uint32_t dst_smem, const void* src) {
    asm volatile("cp.async.cg.shared.global [%0], [%1], 16;" :: "r"(dst_smem), "l"(src));
}
#define CP_COMMIT() asm volatile("cp.async.commit_group;" ::: "memory")
#define CP_WAIT1()  asm volatile("cp.async.wait_group 1;" ::: "memory")
#define CP_WAIT0()  asm volatile("cp.async.wait_group 0;" ::: "memory")

// split f32 pair (x=k, y=k+1) -> packed bf16x2 hi and lo words (k in low half)
__device__ __forceinline__ void split_pair(float x, float y, uint32_t& hw, uint32_t& lw) {
    uint32_t h;
    asm("cvt.rn.bf16x2.f32 %0, %1, %2;" : "=r"(h) : "f"(y), "f"(x));
    float hx = __uint_as_float(h << 16);
    float hy = __uint_as_float(h & 0xffff0000u);
    float lx = x - hx, ly = y - hy;
    asm("cvt.rn.bf16x2.f32 %0, %1, %2;" : "=r"(lw) : "f"(ly), "f"(lx));
    hw = h;
}

__device__ __forceinline__ void ldmx4(uint32_t r[4], uint32_t addr) {
    asm volatile("ldmatrix.sync.aligned.m8n8.x4.shared.b16 {%0,%1,%2,%3}, [%4];"
                 : "=r"(r[0]), "=r"(r[1]), "=r"(r[2]), "=r"(r[3]) : "r"(addr));
}
__device__ __forceinline__ void mma16816(float c[4], const uint32_t a[4], uint32_t b0, uint32_t b1) {
    asm volatile(
        "mma.sync.aligned.m16n8k16.row.col.f32.bf16.bf16.f32 "
        "{%0,%1,%2,%3}, {%4,%5,%6,%7}, {%8,%9}, {%0,%1,%2,%3};"
        : "+f"(c[0]), "+f"(c[1]), "+f"(c[2]), "+f"(c[3])
        : "r"(a[0]), "r"(a[1]), "r"(a[2]), "r"(a[3]), "r"(b0), "r"(b1));
}

// ---------------------------------------------------------------------------
// split-bf16 HMMA GEMM: C[m,n] = sum_k A[m,k] * B[n,k]
//   A: pre-split bf16 hi/lo [rows][ldaE], all K valid (zero-padded)
//   B: f32 [N][ldb], K valid in [0, kvalidB); split to bf16 hi/lo in-loop
//   mode 0: raw f32 partial -> C + z*BATCH*ldc ; fused W row-norms (y==0)
//   mode 1: sigmoid(acc + bias[n]) -> C
// ---------------------------------------------------------------------------
__global__ void __launch_bounds__(NTH, 2)
gemm_hmma(const __nv_bfloat16* __restrict__ Ahi, const __nv_bfloat16* __restrict__ Alo,
          const float* __restrict__ B, const float* __restrict__ bias,
          float* __restrict__ C,
          int N, int ldaE, int ldb, int kvalidB, int ldc,
          int kblk_per_split, int kblk_total, int mode)
{
    extern __shared__ char smem[];
    const uint32_t sb = smem_u32(smem);
    const int tid = threadIdx.x, wid = tid >> 5, lane = tid & 31;
    const int bm = blockIdx.y * BM;
    const int bn = blockIdx.x * BN;
    const int z  = blockIdx.z;
    const int kb0 = z * kblk_per_split;
    int nch = kblk_total - kb0;
    if (nch > kblk_per_split) nch = kblk_per_split;
    if (nch <= 0) return;

    const int wm = wid >> 2;            // 0..1 -> m offset wm*64
    const int wn = wid & 3;             // 0..3 -> n offset wn*32

    // A copy mapping: threads 0-127 -> hi tile rows, 128-255 -> lo tile rows
    const int apart = tid >> 7;
    const int arow  = tid & 127;
    const __nv_bfloat16* Asrc = apart ? Alo : Ahi;

    // B loader mapping: 2 threads per row
    const int crow  = tid >> 1;         // 0..127
    const int chalf = tid & 1;          // 8-float half of the 16-float row
    const int gnB   = bn + crow;
    const int gnBc  = gnB < N ? gnB : N - 1;

    float acc[4][4][4];
    #pragma unroll
    for (int i = 0; i < 4; i++)
        #pragma unroll
        for (int j = 0; j < 4; j++)
            #pragma unroll
            for (int q = 0; q < 4; q++) acc[i][j][q] = 0.f;

    float rn = 0.f;                     // fused row-norm accumulator (mode 0)
    float4 bvE[2], bvO[2];              // ping-pong B prefetch register buffers

    // ---- A tile copy via cp.async (bf16 hi/lo, no conversion) ----
    auto cpA = [&](int c) {
        const uint32_t d = sb + (uint32_t)((c % 3) * A_STAGE + apart * TILE_B + arow * ROWB);
        const char* s = (const char*)(Asrc + (size_t)(bm + arow) * ldaE + (size_t)(kb0 + c) * BK);
        cpa16(d, s);
        cpa16(d + 16, s + 16);
    };
    // ---- B: LDG f32 (2 float4) into a named register buffer ----
    auto ldgB = [&](int c, float4 (&bv)[2]) {
        const int kc = (kb0 + c) * BK + chalf * 8;
        const float* p = B + (size_t)gnBc * ldb + kc;
        #pragma unroll
        for (int j = 0; j < 2; j++) {
            bool ok = (gnB < N) && (kc + j * 4 < kvalidB);
            bv[j] = ok ? *reinterpret_cast<const float4*>(p + j * 4)
                       : make_float4(0.f, 0.f, 0.f, 0.f);
        }
    };
    // ---- B: split + STS (+ fused row-norm) ----
    auto stsB = [&](int c, float4 (&bv)[2]) {
        char* d = smem + SMEM_A_REGION + (c & 1) * B_STAGE + crow * ROWB + chalf * 16;
        uint32_t h[4], l[4];
        split_pair(bv[0].x, bv[0].y, h[0], l[0]);
        split_pair(bv[0].z, bv[0].w, h[1], l[1]);
        split_pair(bv[1].x, bv[1].y, h[2], l[2]);
        split_pair(bv[1].z, bv[1].w, h[3], l[3]);
        if (mode == 0)
            rn += bv[0].x * bv[0].x + bv[0].y * bv[0].y + bv[0].z * bv[0].z + bv[0].w * bv[0].w
                + bv[1].x * bv[1].x + bv[1].y * bv[1].y + bv[1].z * bv[1].z + bv[1].w * bv[1].w;
        *reinterpret_cast<uint4*>(d)          = make_uint4(h[0], h[1], h[2], h[3]);
        *reinterpret_cast<uint4*>(d + TILE_B) = make_uint4(l[0], l[1], l[2], l[3]);
    };

    const int lr = lane & 15;      // row within 16-row tile
    const int lc = lane >> 4;      // 0/1 -> +16B (k8..15 half)

    // ---- compute one chunk (R9 schedule: 12 ldmx4, 48 MMA per warp) ----
    auto computeChunk = [&](int ci) {
        const uint32_t saB = sb + (uint32_t)((ci % 3) * A_STAGE);
        const uint32_t sbB = sb + (uint32_t)(SMEM_A_REGION + (ci & 1) * B_STAGE);
        uint32_t bh[4][2], bl[4][2];
        const uint32_t boff = sbB + (uint32_t)((wn * 32 + lr) * ROWB + lc * 16);
        #pragma unroll
        for (int bt = 0; bt < 2; bt++) {
            uint32_t t[4];
            ldmx4(t, boff + bt * 16 * ROWB);
            bh[bt * 2 + 0][0] = t[0]; bh[bt * 2 + 0][1] = t[2];
            bh[bt * 2 + 1][0] = t[1]; bh[bt * 2 + 1][1] = t[3];
            ldmx4(t, boff + TILE_B + bt * 16 * ROWB);
            bl[bt * 2 + 0][0] = t[0]; bl[bt * 2 + 0][1] = t[2];
            bl[bt * 2 + 1][0] = t[1]; bl[bt * 2 + 1][1] = t[3];
        }
        const uint32_t aoff = saB + (uint32_t)((wm * 64 + lr) * ROWB + lc * 16);
        #pragma unroll
        for (int mi = 0; mi < 4; mi++) {
            uint32_t ah[4], al[4];
            ldmx4(ah, aoff + mi * 16 * ROWB);
            ldmx4(al, aoff + TILE_B + mi * 16 * ROWB);
            #pragma unroll
            for (int ni = 0; ni < 4; ni++)
                mma16816(acc[mi][ni], ah, bh[ni][0], bh[ni][1]);
            #pragma unroll
            for (int ni = 0; ni < 4; ni++)
                mma16816(acc[mi][ni], al, bh[ni][0], bh[ni][1]);
            #pragma unroll
            for (int ni = 0; ni < 4; ni++)
                mma16816(acc[mi][ni], ah, bl[ni][0], bl[ni][1]);
        }
    };

    // ---- prologue ----
    cpA(0); CP_COMMIT();
    if (1 < nch) cpA(1);
    CP_COMMIT();
    ldgB(0, bvE); stsB(0, bvE);          // B(0) staged (visible after first barrier)
    if (1 < nch) ldgB(1, bvO);           // B(1) in flight with a full-iteration lead

// one pipeline step: at iter CI, A(CI) has arrived (cp.async 2 ahead),
// B(CI) was stored last iteration, B(CI+1) regs were fetched last iteration.
#define GEMM_STEP(CI, BVLDG, BVSTS) do {                                  \
        CP_WAIT1();                                                       \
        __syncthreads();                                                  \
        if ((CI) + 2 < nch) cpA((CI) + 2);                                \
        CP_COMMIT();                                                      \
        if ((CI) + 2 < nch) ldgB((CI) + 2, BVLDG);                        \
        if ((CI) + 1 < nch) stsB((CI) + 1, BVSTS);                        \
        computeChunk(CI);                                                 \
    } while (0)

    int ci = 0;
    for (; ci + 1 < nch; ci += 2) {
        GEMM_STEP(ci,     bvE, bvO);     // even: ldg(ci+2)->E, sts(ci+1)<-O
        GEMM_STEP(ci + 1, bvO, bvE);     // odd:  ldg(ci+3)->O, sts(ci+2)<-E
    }
    if (ci < nch) GEMM_STEP(ci, bvE, bvO);
#undef GEMM_STEP
    CP_WAIT0();

    // ---- fused row-norm output (encoder, one grid.y slice only) ----
    if (mode == 0 && blockIdx.y == 0) {
        rn += __shfl_xor_sync(0xffffffffu, rn, 1);
        if (chalf == 0 && gnB < N) atomicAdd(&g_rownorm2[gnB], rn);
    }

    // ---- epilogue ----
    const int er = lane >> 2, ec = (lane & 3) * 2;
    #pragma unroll
    for (int mi = 0; mi < 4; mi++) {
        #pragma unroll
        for (int ni = 0; ni < 4; ni++) {
            int m0 = bm + wm * 64 + mi * 16 + er;
            int n0 = bn + wn * 32 + ni * 8 + ec;
            if (mode == 0) {
                float* Cz = C + (size_t)z * BATCH * ldc;
                if (n0 + 1 < N) {
                    *reinterpret_cast<float2*>(Cz + (size_t)m0 * ldc + n0) =
                        make_float2(acc[mi][ni][0], acc[mi][ni][1]);
                    *reinterpret_cast<float2*>(Cz + (size_t)(m0 + 8) * ldc + n0) =
                        make_float2(acc[mi][ni][2], acc[mi][ni][3]);
                } else if (n0 < N) {
                    Cz[(size_t)m0 * ldc + n0] = acc[mi][ni][0];
                    Cz[(size_t)(m0 + 8) * ldc + n0] = acc[mi][ni][2];
                }
            } else {
                if (n0 + 1 < N) {
                    float b0 = bias[n0], b1 = bias[n0 + 1];
                    *reinterpret_cast<float2*>(C + (size_t)m0 * ldc + n0) =
                        make_float2(sigmoidf_(acc[mi][ni][0] + b0), sigmoidf_(acc[mi][ni][1] + b1));
                    *reinterpret_cast<float2*>(C + (size_t)(m0 + 8) * ldc + n0) =
                        make_float2(sigmoidf_(acc[mi][ni][2] + b0), sigmoidf_(acc[mi][ni][3] + b1));
                } else if (n0 < N) {
                    float b0 = bias[n0];
                    C[(size_t)m0 * ldc + n0] = sigmoidf_(acc[mi][ni][0] + b0);
                    C[(size_t)(m0 + 8) * ldc + n0] = sigmoidf_(acc[mi][ni][2] + b0);
                }
            }
        }
    }
}

// ---------------------------------------------------------------------------
// x f32 -> x_hi/x_lo bf16 ; zero row-norm accumulators + jac
// ---------------------------------------------------------------------------
__global__ void convert_x(const float4* __restrict__ x4, float* __restrict__ jac_init) {
    int i = blockIdx.x * 256 + threadIdx.x;
    if (i < BATCH * INSZ / 4) {
        float4 v = x4[i];
        uint32_t h0, l0, h1, l1;
        split_pair(v.x, v.y, h0, l0);
        split_pair(v.z, v.w, h1, l1);
        reinterpret_cast<uint2*>(g_xhi)[i] = make_uint2(h0, h1);
        reinterpret_cast<uint2*>(g_xlo)[i] = make_uint2(l0, l1);
    }
    if (i < FEAT) g_rownorm2[i] = 0.f;
    if (i == 0) *jac_init = 0.f;
}

// ---------------------------------------------------------------------------
// encoder epilogue: sum split-K partials + bias -> sigmoid -> y_enc hi/lo bf16,
// accumulate jac_reg (row norms came from the fused encoder GEMM)
// ---------------------------------------------------------------------------
__global__ void enc_epilogue(const float* __restrict__ b_enc, float* __restrict__ jac_out) {
    int idx = blockIdx.x * blockDim.x + threadIdx.x;
    float part = 0.f;
    if (idx < BATCH * FEAT_PAD) {
        int m = idx / FEAT_PAD, f = idx % FEAT_PAD;
        if (f < FEAT) {
            float zsum = b_enc[f];
            int base = m * FEAT + f;
            #pragma unroll
            for (int s = 0; s < SPLITK; s++)
                zsum += g_preact[(size_t)s * BATCH * FEAT + base];
            float y = sigmoidf_(zsum);
            __nv_bfloat16 yh = __float2bfloat16_rn(y);
            g_yhi[idx] = yh;
            g_ylo[idx] = __float2bfloat16_rn(y - __bfloat162float(yh));
            float sd = y * (1.f - y);
            part = sd * sd * g_rownorm2[f];
        } else {
            g_yhi[idx] = __float2bfloat16_rn(0.f);
            g_ylo[idx] = __float2bfloat16_rn(0.f);
        }
    }
    #pragma unroll
    for (int o = 16; o > 0; o >>= 1) part += __shfl_down_sync(0xffffffffu, part, o);
    __shared__ float wsum[8];
    int lane = threadIdx.x & 31, wid = threadIdx.x >> 5;
    if (lane == 0) wsum[wid] = part;
    __syncthreads();
    if (wid == 0) {
        float v = (lane < 8) ? wsum[lane] : 0.f;
        #pragma unroll
        for (int o = 4; o > 0; o >>= 1) v += __shfl_down_sync(0xffffffffu, v, o);
        if (lane == 0) atomicAdd(jac_out, v);
    }
}

// ---------------------------------------------------------------------------
extern "C" void kernel_launch(void* const* d_in, const int* in_sizes, int n_in,
                              void* d_out, int out_size) {
    const float* x     = (const float*)d_in[0];
    const float* W_enc = (const float*)d_in[1];
    const float* b_enc = (const float*)d_in[2];
    const float* W_dec = (const float*)d_in[3];
    const float* b_dec = (const float*)d_in[4];
    float* out = (float*)d_out;
    float* jac = out + (out_size - 1);

    float* preact;
    __nv_bfloat16 *xhi, *xlo, *yhi, *ylo;
    cudaGetSymbolAddress((void**)&preact, g_preact);
    cudaGetSymbolAddress((void**)&xhi, g_xhi);
    cudaGetSymbolAddress((void**)&xlo, g_xlo);
    cudaGetSymbolAddress((void**)&yhi, g_yhi);
    cudaGetSymbolAddress((void**)&ylo, g_ylo);

    cudaFuncSetAttribute(gemm_hmma, cudaFuncAttributeMaxDynamicSharedMemorySize, SMEM_TOTAL);

    // 1) x -> bf16 hi/lo split; zero rownorm + jac
    convert_x<<<(BATCH * INSZ / 4 + 255) / 256, 256>>>((const float4*)x, jac);

    // 2) encoder GEMM (fused W_enc row norms): split-K=12 -> 288 CTAs
    {
        dim3 grid((FEAT + BN - 1) / BN, BATCH / BM, SPLITK);   // (12, 2, 12)
        gemm_hmma<<<grid, NTH, SMEM_TOTAL>>>(
            xhi, xlo, W_enc, nullptr, preact,
            FEAT, INSZ, INSZ, INSZ, FEAT,
            ENC_KBLK_PER_SPLIT, ENC_KBLK_TOTAL, 0);
    }

    // 3) bias + sigmoid -> y_enc hi/lo bf16; jacobian reduction
    enc_epilogue<<<(BATCH * FEAT_PAD + 255) / 256, 256>>>(b_enc, jac);

    // 4) decoder GEMM with fused bias+sigmoid
    {
        dim3 grid((INSZ + BN - 1) / BN, BATCH / BM, 1);        // (221, 2, 1)
        gemm_hmma<<<grid, NTH, SMEM_TOTAL>>>(
            yhi, ylo, W_dec, b_dec, out,
            INSZ, FEAT_PAD, FEAT, FEAT, INSZ,
            DEC_KBLK, DEC_KBLK, 1);
    }
}

// round 13
// speedup vs baseline: 1.2867x; 1.1390x over previous
#include <cuda_runtime.h>
#include <cuda_bf16.h>
#include <cstdint>

// ---------------- problem constants ----------------
#define BATCH    256
#define FEAT     1500
#define FEAT_PAD 1536          // 96 * 16, padded K for decoder (zero-filled)
#define INSZ     28224
#define SPLITK   12
#define ENC_KBLK_TOTAL 1764    // 28224 / 16
#define ENC_KBLK_PER_SPLIT 147 // 12 * 147 = 1764 exactly
#define DEC_KBLK 96            // 1536 / 16

// ---------------- GEMM tile config -----------------
#define BM 128
#define BN 128
#define BK 16                  // K elements per chunk
#define NTH 256                // 8 warps: 2 (M) x 4 (N), warp tile 64x32

// smem: 4 tiles per stage (Ah, Al, Bh, Bl), each 128 rows x 16 bf16, row padded
// to 48B -> ldmatrix 8-row groups hit 8 distinct 16B segments (conflict-free)
#define ROWB   48
#define TILE_B (128 * ROWB)    // 6144
#define STAGE_B (4 * TILE_B)   // 24576
#define SMEM_TOTAL (2 * STAGE_B)  // 49152 -> 2 CTAs = 96KB/SM

#define OFF_AH 0
#define OFF_AL TILE_B
#define OFF_BH (2 * TILE_B)
#define OFF_BL (3 * TILE_B)

// ---------------- scratch ----------------
__device__ float g_preact[SPLITK * BATCH * FEAT];      // 18.4 MB
__device__ __align__(256) __nv_bfloat16 g_xhi[BATCH * INSZ];
__device__ __align__(256) __nv_bfloat16 g_xlo[BATCH * INSZ];
__device__ __align__(256) __nv_bfloat16 g_yhi[BATCH * FEAT_PAD];
__device__ __align__(256) __nv_bfloat16 g_ylo[BATCH * FEAT_PAD];
__device__ float g_rownorm2[FEAT];

// ---------------- helpers ----------------
__device__ __forceinline__ uint32_t smem_u32(const void* p) {
    uint32_t a;
    asm("{ .reg .u64 t; cvta.to.shared.u64 t, %1; cvt.u32.u64 %0, t; }" : "=r"(a) : "l"(p));
    return a;
}
__device__ __forceinline__ float sigmoidf_(float z) { return 1.0f / (1.0f + __expf(-z)); }

// split f32 pair (x=k, y=k+1) into packed bf16x2 hi and lo words (k in low half)
__device__ __forceinline__ void split_pair(float x, float y, uint32_t& hw, uint32_t& lw) {
    uint32_t h;
    asm("cvt.rn.bf16x2.f32 %0, %1, %2;" : "=r"(h) : "f"(y), "f"(x));
    float hx = __uint_as_float(h << 16);
    float hy = __uint_as_float(h & 0xffff0000u);
    float lx = x - hx, ly = y - hy;
    asm("cvt.rn.bf16x2.f32 %0, %1, %2;" : "=r"(lw) : "f"(ly), "f"(lx));
    hw = h;
}

__device__ __forceinline__ void ldmx4(uint32_t r[4], uint32_t addr) {
    asm volatile("ldmatrix.sync.aligned.m8n8.x4.shared.b16 {%0,%1,%2,%3}, [%4];"
                 : "=r"(r[0]), "=r"(r[1]), "=r"(r[2]), "=r"(r[3]) : "r"(addr));
}
__device__ __forceinline__ void mma16816(float c[4], const uint32_t a[4], uint32_t b0, uint32_t b1) {
    asm volatile(
        "mma.sync.aligned.m16n8k16.row.col.f32.bf16.bf16.f32 "
        "{%0,%1,%2,%3}, {%4,%5,%6,%7}, {%8,%9}, {%0,%1,%2,%3};"
        : "+f"(c[0]), "+f"(c[1]), "+f"(c[2]), "+f"(c[3])
        : "r"(a[0]), "r"(a[1]), "r"(a[2]), "r"(a[3]), "r"(b0), "r"(b1));
}

// ---------------------------------------------------------------------------
// split-bf16 HMMA GEMM (R9 schedule): C[m,n] = sum_k A[m,k] * B[n,k]
//   A: pre-split bf16 hi/lo [rows][ldaE], all K valid (zero-padded)
//   B: f32 [N][ldb], K valid in [0, kvalidB)
//   mode 0: raw f32 partial -> C + z*BATCH*ldc ; fused W row-norms (y==0)
//   mode 1: sigmoid(acc + bias[n]) -> C
// ---------------------------------------------------------------------------
__global__ void __launch_bounds__(NTH, 2)
gemm_hmma(const __nv_bfloat16* __restrict__ Ahi, const __nv_bfloat16* __restrict__ Alo,
          const float* __restrict__ B, const float* __restrict__ bias,
          float* __restrict__ C,
          int N, int ldaE, int ldb, int kvalidB, int ldc,
          int kblk_per_split, int kblk_total, int mode)
{
    extern __shared__ char smem[];
    const uint32_t sb = smem_u32(smem);
    const int tid = threadIdx.x, wid = tid >> 5, lane = tid & 31;
    const int bm = blockIdx.y * BM;
    const int bn = blockIdx.x * BN;
    const int z  = blockIdx.z;
    const int kb0 = z * kblk_per_split;
    int nch = kblk_total - kb0;
    if (nch > kblk_per_split) nch = kblk_per_split;
    if (nch <= 0) return;

    const int wm = wid >> 2;        // 0..1 -> m offset wm*64
    const int wn = wid & 3;         // 0..3 -> n offset wn*32

    // loader: thread -> (row = tid>>2 (+64 per iter), quarter q = tid&3)
    const int lrow = tid >> 2;          // 0..63
    const int lq   = tid & 3;           // 4-element group along K (0..3)
    const bool do_rn = (mode == 0) && (blockIdx.y == 0);

    float acc[4][4][4];
    #pragma unroll
    for (int i = 0; i < 4; i++)
        #pragma unroll
        for (int j = 0; j < 4; j++)
            #pragma unroll
            for (int q = 0; q < 4; q++) acc[i][j][q] = 0.f;

    uint2 pah[2], pal[2];    // A prefetch (pre-split bf16 hi/lo, 4 elems each)
    float4 pb[2];            // B prefetch (f32)
    float rn0 = 0.f, rn1 = 0.f;   // fused row-norm partials (rows lrow, lrow+64)

    // ---- prefetch chunk 0 ----
    {
        const int kc = kb0 * BK + lq * 4;
        #pragma unroll
        for (int it = 0; it < 2; it++) {
            int row = lrow + it * 64;
            size_t eoff = (size_t)(bm + row) * ldaE + kc;
            pah[it] = *reinterpret_cast<const uint2*>(Ahi + eoff);
            pal[it] = *reinterpret_cast<const uint2*>(Alo + eoff);
            int gn = bn + row;
            float4 v = make_float4(0.f, 0.f, 0.f, 0.f);
            if (gn < N && kc < kvalidB)
                v = *reinterpret_cast<const float4*>(B + (size_t)gn * ldb + kc);
            pb[it] = v;
        }
    }
    // ---- STS chunk 0 into buf 0 ----
    {
        char* st = smem;
        #pragma unroll
        for (int it = 0; it < 2; it++) {
            int row = lrow + it * 64;
            uint32_t off = (uint32_t)(row * ROWB + lq * 8);
            *reinterpret_cast<uint2*>(st + OFF_AH + off) = pah[it];
            *reinterpret_cast<uint2*>(st + OFF_AL + off) = pal[it];
            uint32_t hw0, lw0, hw1, lw1;
            split_pair(pb[it].x, pb[it].y, hw0, lw0);
            split_pair(pb[it].z, pb[it].w, hw1, lw1);
            *reinterpret_cast<uint2*>(st + OFF_BH + off) = make_uint2(hw0, hw1);
            *reinterpret_cast<uint2*>(st + OFF_BL + off) = make_uint2(lw0, lw1);
        }
        if (do_rn) {
            rn0 += pb[0].x * pb[0].x + pb[0].y * pb[0].y + pb[0].z * pb[0].z + pb[0].w * pb[0].w;
            rn1 += pb[1].x * pb[1].x + pb[1].y * pb[1].y + pb[1].z * pb[1].z + pb[1].w * pb[1].w;
        }
    }

    const int lr = lane & 15;          // row within 16-row tile
    const int lc = lane >> 4;          // 0/1 -> +16B (k8..k15 half)

    for (int ci = 0; ci < nch; ci++) {
        __syncthreads();   // STS(ci) visible; compute(ci-1) done

        // prefetch chunk ci+1 (held in regs during compute)
        if (ci + 1 < nch) {
            const int kc = (kb0 + ci + 1) * BK + lq * 4;
            #pragma unroll
            for (int it = 0; it < 2; it++) {
                int row = lrow + it * 64;
                size_t eoff = (size_t)(bm + row) * ldaE + kc;
                pah[it] = *reinterpret_cast<const uint2*>(Ahi + eoff);
                pal[it] = *reinterpret_cast<const uint2*>(Alo + eoff);
                int gn = bn + row;
                float4 v = make_float4(0.f, 0.f, 0.f, 0.f);
                if (gn < N && kc < kvalidB)
                    v = *reinterpret_cast<const float4*>(B + (size_t)gn * ldb + kc);
                pb[it] = v;
            }
        }

        // ---- compute chunk ci from buf ci&1 (identical to R9) ----
        const uint32_t stg = sb + (uint32_t)((ci & 1) * STAGE_B);
        {
            uint32_t bh[4][2], bl[4][2];
            const uint32_t b_off = stg + (uint32_t)((wn * 32 + lr) * ROWB + lc * 16);
            #pragma unroll
            for (int bt = 0; bt < 2; bt++) {
                uint32_t t[4];
                ldmx4(t, b_off + OFF_BH + bt * 16 * ROWB);
                bh[bt * 2 + 0][0] = t[0]; bh[bt * 2 + 0][1] = t[2];
                bh[bt * 2 + 1][0] = t[1]; bh[bt * 2 + 1][1] = t[3];
                ldmx4(t, b_off + OFF_BL + bt * 16 * ROWB);
                bl[bt * 2 + 0][0] = t[0]; bl[bt * 2 + 0][1] = t[2];
                bl[bt * 2 + 1][0] = t[1]; bl[bt * 2 + 1][1] = t[3];
            }
            const uint32_t a_off = stg + (uint32_t)((wm * 64 + lr) * ROWB + lc * 16);
            #pragma unroll
            for (int mi = 0; mi < 4; mi++) {
                uint32_t ah[4], al[4];
                ldmx4(ah, a_off + OFF_AH + mi * 16 * ROWB);
                ldmx4(al, a_off + OFF_AL + mi * 16 * ROWB);
                #pragma unroll
                for (int ni = 0; ni < 4; ni++)
                    mma16816(acc[mi][ni], ah, bh[ni][0], bh[ni][1]);
                #pragma unroll
                for (int ni = 0; ni < 4; ni++)
                    mma16816(acc[mi][ni], al, bh[ni][0], bh[ni][1]);
                #pragma unroll
                for (int ni = 0; ni < 4; ni++)
                    mma16816(acc[mi][ni], ah, bl[ni][0], bl[ni][1]);
            }
        }

        // ---- STS chunk ci+1 into other buffer (R9 position) ----
        if (ci + 1 < nch) {
            char* st = smem + ((ci + 1) & 1) * STAGE_B;
            #pragma unroll
            for (int it = 0; it < 2; it++) {
                int row = lrow + it * 64;
                uint32_t off = (uint32_t)(row * ROWB + lq * 8);
                *reinterpret_cast<uint2*>(st + OFF_AH + off) = pah[it];
                *reinterpret_cast<uint2*>(st + OFF_AL + off) = pal[it];
                uint32_t hw0, lw0, hw1, lw1;
                split_pair(pb[it].x, pb[it].y, hw0, lw0);
                split_pair(pb[it].z, pb[it].w, hw1, lw1);
                *reinterpret_cast<uint2*>(st + OFF_BH + off) = make_uint2(hw0, hw1);
                *reinterpret_cast<uint2*>(st + OFF_BL + off) = make_uint2(lw0, lw1);
            }
            if (do_rn) {
                rn0 += pb[0].x * pb[0].x + pb[0].y * pb[0].y + pb[0].z * pb[0].z + pb[0].w * pb[0].w;
                rn1 += pb[1].x * pb[1].x + pb[1].y * pb[1].y + pb[1].z * pb[1].z + pb[1].w * pb[1].w;
            }
        }
    }

    // ---- fused row-norm output (encoder, bm slice 0 only) ----
    if (do_rn) {
        rn0 += __shfl_xor_sync(0xffffffffu, rn0, 1);
        rn0 += __shfl_xor_sync(0xffffffffu, rn0, 2);
        rn1 += __shfl_xor_sync(0xffffffffu, rn1, 1);
        rn1 += __shfl_xor_sync(0xffffffffu, rn1, 2);
        if (lq == 0) {
            int r0 = bn + lrow, r1 = bn + lrow + 64;
            if (r0 < N) atomicAdd(&g_rownorm2[r0], rn0);
            if (r1 < N) atomicAdd(&g_rownorm2[r1], rn1);
        }
    }

    // ---- epilogue (identical to R9) ----
    const int er = lane >> 2, ec = (lane & 3) * 2;
    #pragma unroll
    for (int mi = 0; mi < 4; mi++) {
        #pragma unroll
        for (int ni = 0; ni < 4; ni++) {
            int m0 = bm + wm * 64 + mi * 16 + er;
            int n0 = bn + wn * 32 + ni * 8 + ec;
            if (mode == 0) {
                float* Cz = C + (size_t)z * BATCH * ldc;
                if (n0 + 1 < N) {
                    *reinterpret_cast<float2*>(Cz + (size_t)m0 * ldc + n0) =
                        make_float2(acc[mi][ni][0], acc[mi][ni][1]);
                    *reinterpret_cast<float2*>(Cz + (size_t)(m0 + 8) * ldc + n0) =
                        make_float2(acc[mi][ni][2], acc[mi][ni][3]);
                } else if (n0 < N) {
                    Cz[(size_t)m0 * ldc + n0] = acc[mi][ni][0];
                    Cz[(size_t)(m0 + 8) * ldc + n0] = acc[mi][ni][2];
                }
            } else {
                if (n0 + 1 < N) {
                    float b0 = bias[n0], b1 = bias[n0 + 1];
                    *reinterpret_cast<float2*>(C + (size_t)m0 * ldc + n0) =
                        make_float2(sigmoidf_(acc[mi][ni][0] + b0), sigmoidf_(acc[mi][ni][1] + b1));
                    *reinterpret_cast<float2*>(C + (size_t)(m0 + 8) * ldc + n0) =
                        make_float2(sigmoidf_(acc[mi][ni][2] + b0), sigmoidf_(acc[mi][ni][3] + b1));
                } else if (n0 < N) {
                    float b0 = bias[n0];
                    C[(size_t)m0 * ldc + n0] = sigmoidf_(acc[mi][ni][0] + b0);
                    C[(size_t)(m0 + 8) * ldc + n0] = sigmoidf_(acc[mi][ni][2] + b0);
                }
            }
        }
    }
}

// ---------------------------------------------------------------------------
// x f32 -> x_hi/x_lo bf16 ; zero row-norm accumulators + jac
// ---------------------------------------------------------------------------
__global__ void convert_x(const float4* __restrict__ x4, float* __restrict__ jac_init) {
    int i = blockIdx.x * 256 + threadIdx.x;
    if (i < BATCH * INSZ / 4) {
        float4 v = x4[i];
        uint32_t h0, l0, h1, l1;
        split_pair(v.x, v.y, h0, l0);
        split_pair(v.z, v.w, h1, l1);
        reinterpret_cast<uint2*>(g_xhi)[i] = make_uint2(h0, h1);
        reinterpret_cast<uint2*>(g_xlo)[i] = make_uint2(l0, l1);
    }
    if (i < FEAT) g_rownorm2[i] = 0.f;
    if (i == 0) *jac_init = 0.f;
}

// ---------------------------------------------------------------------------
// encoder epilogue: sum split-K partials + bias -> sigmoid -> y_enc hi/lo bf16,
// accumulate jac_reg (row norms came from the fused encoder GEMM)
// ---------------------------------------------------------------------------
__global__ void enc_epilogue(const float* __restrict__ b_enc, float* __restrict__ jac_out) {
    int idx = blockIdx.x * blockDim.x + threadIdx.x;
    float part = 0.f;
    if (idx < BATCH * FEAT_PAD) {
        int m = idx / FEAT_PAD, f = idx % FEAT_PAD;
        if (f < FEAT) {
            float zsum = b_enc[f];
            int base = m * FEAT + f;
            #pragma unroll
            for (int s = 0; s < SPLITK; s++)
                zsum += g_preact[(size_t)s * BATCH * FEAT + base];
            float y = sigmoidf_(zsum);
            __nv_bfloat16 yh = __float2bfloat16_rn(y);
            g_yhi[idx] = yh;
            g_ylo[idx] = __float2bfloat16_rn(y - __bfloat162float(yh));
            float sd = y * (1.f - y);
            part = sd * sd * g_rownorm2[f];
        } else {
            g_yhi[idx] = __float2bfloat16_rn(0.f);
            g_ylo[idx] = __float2bfloat16_rn(0.f);
        }
    }
    #pragma unroll
    for (int o = 16; o > 0; o >>= 1) part += __shfl_down_sync(0xffffffffu, part, o);
    __shared__ float wsum[8];
    int lane = threadIdx.x & 31, wid = threadIdx.x >> 5;
    if (lane == 0) wsum[wid] = part;
    __syncthreads();
    if (wid == 0) {
        float v = (lane < 8) ? wsum[lane] : 0.f;
        #pragma unroll
        for (int o = 4; o > 0; o >>= 1) v += __shfl_down_sync(0xffffffffu, v, o);
        if (lane == 0) atomicAdd(jac_out, v);
    }
}

// ---------------------------------------------------------------------------
extern "C" void kernel_launch(void* const* d_in, const int* in_sizes, int n_in,
                              void* d_out, int out_size) {
    const float* x     = (const float*)d_in[0];
    const float* W_enc = (const float*)d_in[1];
    const float* b_enc = (const float*)d_in[2];
    const float* W_dec = (const float*)d_in[3];
    const float* b_dec = (const float*)d_in[4];
    float* out = (float*)d_out;
    float* jac = out + (out_size - 1);

    float* preact;
    __nv_bfloat16 *xhi, *xlo, *yhi, *ylo;
    cudaGetSymbolAddress((void**)&preact, g_preact);
    cudaGetSymbolAddress((void**)&xhi, g_xhi);
    cudaGetSymbolAddress((void**)&xlo, g_xlo);
    cudaGetSymbolAddress((void**)&yhi, g_yhi);
    cudaGetSymbolAddress((void**)&ylo, g_ylo);

    cudaFuncSetAttribute(gemm_hmma, cudaFuncAttributeMaxDynamicSharedMemorySize, SMEM_TOTAL);

    // 1) x -> bf16 hi/lo split; zero rownorm + jac
    convert_x<<<(BATCH * INSZ / 4 + 255) / 256, 256>>>((const float4*)x, jac);

    // 2) encoder GEMM (fused W_enc row norms): split-K=12 -> 288 CTAs
    {
        dim3 grid((FEAT + BN - 1) / BN, BATCH / BM, SPLITK);   // (12, 2, 12)
        gemm_hmma<<<grid, NTH, SMEM_TOTAL>>>(
            xhi, xlo, W_enc, nullptr, preact,
            FEAT, INSZ, INSZ, INSZ, FEAT,
            ENC_KBLK_PER_SPLIT, ENC_KBLK_TOTAL, 0);
    }

    // 3) bias + sigmoid -> y_enc hi/lo bf16; jacobian reduction
    enc_epilogue<<<(BATCH * FEAT_PAD + 255) / 256, 256>>>(b_enc, jac);

    // 4) decoder GEMM with fused bias+sigmoid
    {
        dim3 grid((INSZ + BN - 1) / BN, BATCH / BM, 1);        // (221, 2, 1)
        gemm_hmma<<<grid, NTH, SMEM_TOTAL>>>(
            yhi, ylo, W_dec, b_dec, out,
            INSZ, FEAT_PAD, FEAT, FEAT, INSZ,
            DEC_KBLK, DEC_KBLK, 1);
    }
}